// round 8
// baseline (speedup 1.0000x reference)
#include <cuda_runtime.h>
#include <cstdint>
#include <cstddef>

#define BB 4
#define TT 32
#define NN 1024
#define KK 16
#define HD 128

// d_out layout (float32, concatenated outputs):
//   out1: [B][T][132][N]      17,301,504
//   h:    [B][128][N]            524,288   @ 17,301,504
//   c:    [B][128][N]            524,288   @ 17,825,792
//   gidx: [B][T][N][K] (cast)  2,097,152   @ 18,350,080
#define OFF_H 17301504
#define OFF_C 17825792
#define OFF_I 18350080

#define SBT (BB*NN*HD)   // per-timestep h/c slab: 524288

// ---------------- device scratch (static, allowed) ----------------
__device__ float g_U[BB*NN*512];
__device__ float g_V[BB*NN*512];
__device__ float g_hs0[(size_t)TT*BB*NN*HD];  // [t][b][n][j]
__device__ float g_hs1[(size_t)TT*BB*NN*HD];
__device__ float g_c[2][BB*NN*HD];            // ping-pong, [b][n][j]
__device__ int   g_idx[BB*TT*NN*KK];
__device__ float g_Wd0[512*4];
__device__ float g_Wd1[512*4];

// ---------------- fast math helpers ----------------
__device__ __forceinline__ float sigf(float x) {
    return __fdividef(1.0f, 1.0f + __expf(-x));
}
__device__ __forceinline__ float tanh_f(float x) {
    // 2*sigmoid(2x)-1 : safe at both tails (exp->inf gives -1, exp->0 gives 1)
    return fmaf(2.0f, __fdividef(1.0f, 1.0f + __expf(-2.0f * x)), -1.0f);
}

// ---------------- KNN: stable top-16 smallest d2 ----------------
// Rounding carefully matches XLA's fp32 emission:
//   q2/r2: separate mul + add ops (NO fma contraction)  -> __fmul_rn/__fadd_rn
//   qr:    cublas-style fma accumulation chain from 0
//   d2:    fl( fl(q2 + r2) - 2*qr )   (2*qr exact, power of two)
__global__ __launch_bounds__(256) void knn_kernel(const float* __restrict__ x) {
    __shared__ float rx[NN], ry[NN], rz[NN], rr[NN];
    int t = blockIdx.y, b = blockIdx.z;
    int f = t ? t - 1 : 0;
    const float* rb = x + ((size_t)(b*TT + f) * 4) * NN;
    for (int i = threadIdx.x; i < NN; i += 256) {
        float a = rb[i], bb = rb[NN + i], cc = rb[2*NN + i];
        rx[i] = a; ry[i] = bb; rz[i] = cc;
        float s = __fadd_rn(__fmul_rn(a, a), __fmul_rn(bb, bb));
        rr[i] = __fadd_rn(s, __fmul_rn(cc, cc));
    }
    __syncthreads();

    int n = blockIdx.x * 256 + threadIdx.x;
    const float* qb = x + ((size_t)(b*TT + t) * 4) * NN;
    float qx = qb[n], qy = qb[NN + n], qz = qb[2*NN + n];
    float q2 = __fadd_rn(__fadd_rn(__fmul_rn(qx, qx), __fmul_rn(qy, qy)),
                         __fmul_rn(qz, qz));

    float bd[KK]; int bi[KK];
#pragma unroll
    for (int k = 0; k < KK; ++k) { bd[k] = 3.402823466e38f; bi[k] = 0; }

    for (int m = 0; m < NN; ++m) {
        // qr: fma chain (k ascending, start from 0) as cublas SGEMM accumulates
        float qr = __fmaf_rn(qz, rz[m],
                    __fmaf_rn(qy, ry[m],
                     __fmaf_rn(qx, rx[m], 0.0f)));
        float d  = __fsub_rn(__fadd_rn(q2, rr[m]), __fmul_rn(2.0f, qr));
        if (d < bd[KK-1]) {
            bd[KK-1] = d; bi[KK-1] = m;
#pragma unroll
            for (int jj = KK-1; jj > 0; --jj) {
                if (bd[jj] < bd[jj-1]) {  // strict: stable w.r.t. ties (lower idx first)
                    float td = bd[jj]; bd[jj] = bd[jj-1]; bd[jj-1] = td;
                    int   ti = bi[jj]; bi[jj] = bi[jj-1]; bi[jj-1] = ti;
                }
            }
        }
    }
    int* op = g_idx + (((size_t)b*TT + t) * NN + n) * KK;
#pragma unroll
    for (int k = 0; k < KK; ++k) op[k] = bi[k];
}

// ---------------- weight prep: Wd = Wx[:, :4] - Wpd ----------------
__global__ void wdiff_kernel(const float* __restrict__ w0, const float* __restrict__ w1) {
    int o = blockIdx.x * 128 + threadIdx.x;
    if (o < 512) {
#pragma unroll
        for (int c = 0; c < 4; ++c) {
            g_Wd0[o*4 + c] = w0[o*136 + c] - w0[o*136 + 4 + c];
            g_Wd1[o*4 + c] = w1[o*264 + c] - w1[o*264 + 132 + c];
        }
    }
}

// ---------------- GEMM: Out[b][m][o] = Wp(4ch)*pos + Wh(128ch)*H + bias ----------------
// modes: 0 = U layer0, 1 = V layer0 (pos only), 2 = U layer1, 3 = V layer1
__global__ __launch_bounds__(256) void gemm_kernel(
    int mode, int t,
    const float* __restrict__ x,
    const float* __restrict__ w0, const float* __restrict__ b0,
    const float* __restrict__ w1, const float* __restrict__ b1)
{
    const float* Wp;  int ldp;
    const float* Wh = nullptr; int ldh = 0;
    const float* bias = nullptr;
    const float* H = nullptr;
    float* Out;
    int frame;
    if (mode == 0) {
        Wp = w0 + 4; ldp = 136; Wh = w0 + 8; ldh = 136;
        frame = t ? t - 1 : 0;
        H = t ? (g_hs0 + (size_t)(t-1) * SBT) : nullptr;
        Out = g_U;
    } else if (mode == 1) {
        Wp = g_Wd0; ldp = 4; bias = b0; frame = t; Out = g_V;
    } else if (mode == 2) {
        Wp = w1 + 132; ldp = 264; Wh = w1 + 136; ldh = 264;
        frame = t ? t - 1 : 0;
        H = t ? (g_hs1 + (size_t)(t-1) * SBT) : nullptr;
        Out = g_U;
    } else {
        Wp = g_Wd1; ldp = 4; Wh = w1 + 4; ldh = 264; bias = b1;
        frame = t; H = g_hs0 + (size_t)t * SBT; Out = g_V;
    }

    __shared__ float sWp[4][64];
    __shared__ float sP [4][128];
    __shared__ float sW [16][68];
    __shared__ float sIn[16][132];

    int tid = threadIdx.x;
    int b   = blockIdx.z;
    int o0  = blockIdx.x * 64;
    int m0  = blockIdx.y * 128;
    int of  = (tid & 15) * 4;   // 4 outputs per thread
    int mf  = (tid >> 4) * 8;   // 8 points per thread

    const float* Pb = x + ((size_t)(b*TT + frame) * 4) * NN + m0;
    for (int i = tid; i < 512; i += 256)
        sP[i >> 7][i & 127] = Pb[(size_t)(i >> 7) * NN + (i & 127)];
    {
        int c = tid >> 6, oo = tid & 63;
        sWp[c][oo] = Wp[(size_t)(o0 + oo) * ldp + c];
    }
    __syncthreads();

    float acc[8][4];
    {
        float bv0 = 0.f, bv1 = 0.f, bv2 = 0.f, bv3 = 0.f;
        if (bias) { bv0 = bias[o0+of]; bv1 = bias[o0+of+1]; bv2 = bias[o0+of+2]; bv3 = bias[o0+of+3]; }
#pragma unroll
        for (int mi = 0; mi < 8; ++mi) { acc[mi][0]=bv0; acc[mi][1]=bv1; acc[mi][2]=bv2; acc[mi][3]=bv3; }
    }

    // position (4-channel) contribution
#pragma unroll
    for (int c = 0; c < 4; ++c) {
        float a0 = sWp[c][of], a1 = sWp[c][of+1], a2 = sWp[c][of+2], a3 = sWp[c][of+3];
#pragma unroll
        for (int mi = 0; mi < 8; ++mi) {
            float p = sP[c][mf + mi];
            acc[mi][0] = fmaf(a0, p, acc[mi][0]);
            acc[mi][1] = fmaf(a1, p, acc[mi][1]);
            acc[mi][2] = fmaf(a2, p, acc[mi][2]);
            acc[mi][3] = fmaf(a3, p, acc[mi][3]);
        }
    }

    // hidden (128-channel) contribution; H layout [b][m][j] (j contiguous)
    if (Wh && H) {
        const float* Hb = H + ((size_t)b * NN + m0) * HD;
        for (int k0 = 0; k0 < HD; k0 += 16) {
            {   // W tile: 64 o x 16 k
                int oo = tid >> 2, j4 = (tid & 3) * 4;
                float4 wv = *reinterpret_cast<const float4*>(Wh + (size_t)(o0 + oo) * ldh + k0 + j4);
                sW[j4  ][oo] = wv.x; sW[j4+1][oo] = wv.y;
                sW[j4+2][oo] = wv.z; sW[j4+3][oo] = wv.w;
            }
            {   // In tile (transposed load): 16 k x 128 m
                int mm = tid >> 1, half = tid & 1;
                const float* hp = Hb + (size_t)mm * HD + k0 + half * 8;
                float4 h0 = *reinterpret_cast<const float4*>(hp);
                float4 h1 = *reinterpret_cast<const float4*>(hp + 4);
                int kk = half * 8;
                sIn[kk  ][mm] = h0.x; sIn[kk+1][mm] = h0.y; sIn[kk+2][mm] = h0.z; sIn[kk+3][mm] = h0.w;
                sIn[kk+4][mm] = h1.x; sIn[kk+5][mm] = h1.y; sIn[kk+6][mm] = h1.z; sIn[kk+7][mm] = h1.w;
            }
            __syncthreads();
#pragma unroll
            for (int k = 0; k < 16; ++k) {
                float4 a  = *reinterpret_cast<const float4*>(&sW[k][of]);
                float4 p0 = *reinterpret_cast<const float4*>(&sIn[k][mf]);
                float4 p1 = *reinterpret_cast<const float4*>(&sIn[k][mf+4]);
                float pb[8] = {p0.x,p0.y,p0.z,p0.w,p1.x,p1.y,p1.z,p1.w};
#pragma unroll
                for (int mi = 0; mi < 8; ++mi) {
                    acc[mi][0] = fmaf(a.x, pb[mi], acc[mi][0]);
                    acc[mi][1] = fmaf(a.y, pb[mi], acc[mi][1]);
                    acc[mi][2] = fmaf(a.z, pb[mi], acc[mi][2]);
                    acc[mi][3] = fmaf(a.w, pb[mi], acc[mi][3]);
                }
            }
            __syncthreads();
        }
    }

    float* Ob = Out + ((size_t)b * NN + m0 + mf) * 512 + o0 + of;
#pragma unroll
    for (int mi = 0; mi < 8; ++mi) {
        float4 v = make_float4(acc[mi][0], acc[mi][1], acc[mi][2], acc[mi][3]);
        *reinterpret_cast<float4*>(Ob + (size_t)mi * 512) = v;
    }
}

// ---------------- gate + max-over-K ----------------
__global__ __launch_bounds__(128) void gate_kernel(int t, int layer) {
    int n = blockIdx.x, b = blockIdx.y;
    int j = threadIdx.x;
    __shared__ int sm[KK];
    if (j < KK) sm[j] = g_idx[(((size_t)b*TT + t) * NN + n) * KK + j];
    __syncthreads();

    const float* Vp = g_V + ((size_t)b * NN + n) * 512;
    float v0 = Vp[j], v1 = Vp[HD + j], v2 = Vp[2*HD + j], v3 = Vp[3*HD + j];
    const float* Cprev = t ? g_c[(t-1) & 1] : nullptr;

    float hmax = -1e30f, cmax = -1e30f;
#pragma unroll 4
    for (int k = 0; k < KK; ++k) {
        int m = sm[k];
        const float* Up = g_U + ((size_t)b * NN + m) * 512;
        float gi = v0 + Up[j];
        float gf = v1 + Up[HD + j];
        float go = v2 + Up[2*HD + j];
        float gg = v3 + Up[3*HD + j];
        float cg = Cprev ? Cprev[((size_t)b * NN + m) * HD + j] : 0.0f;
        float cn = fmaf(sigf(gf), cg, sigf(gi) * tanh_f(gg));
        float hn = sigf(go) * tanh_f(cn);
        hmax = fmaxf(hmax, hn);
        cmax = fmaxf(cmax, cn);
    }
    size_t o = ((size_t)b * NN + n) * HD + j;
    float* Hout = (layer ? g_hs1 : g_hs0) + (size_t)t * SBT;
    Hout[o] = hmax;
    g_c[t & 1][o] = cmax;
}

// ---------------- output assembly ----------------
__global__ void out1_pos_kernel(const float* __restrict__ x, float* __restrict__ out) {
    int i = blockIdx.x * 256 + threadIdx.x;  // B*T*4*N = 524288
    if (i < BB*TT*4*NN) {
        int bt = i >> 12;
        int r  = i & 4095;
        out[(size_t)bt * 132 * NN + r] = x[i];
    }
}

__global__ void out1_hs_kernel(float* __restrict__ out) {
    __shared__ float tile[32][33];
    int n0 = blockIdx.x * 32, j0 = blockIdx.y * 32, bt = blockIdx.z;
    int b = bt >> 5, t = bt & 31;
    int tx = threadIdx.x, ty = threadIdx.y;
    tile[ty][tx] = g_hs1[(((size_t)t*BB + b) * NN + n0 + ty) * HD + j0 + tx];
    __syncthreads();
    out[((size_t)bt * 132 + 4 + j0 + ty) * NN + n0 + tx] = tile[tx][ty];
}

__global__ void hc_kernel(float* __restrict__ out) {
    __shared__ float th[32][33];
    __shared__ float tc[32][33];
    int n0 = blockIdx.x * 32, j0 = blockIdx.y * 32, b = blockIdx.z;
    int tx = threadIdx.x, ty = threadIdx.y;
    th[ty][tx] = g_hs1[(((size_t)(TT-1)*BB + b) * NN + n0 + ty) * HD + j0 + tx];
    tc[ty][tx] = g_c[(TT-1) & 1][((size_t)b * NN + n0 + ty) * HD + j0 + tx];
    __syncthreads();
    size_t dst = ((size_t)b * HD + j0 + ty) * NN + n0 + tx;
    out[OFF_H + dst] = th[tx][ty];
    out[OFF_C + dst] = tc[tx][ty];
}

__global__ void idxf_kernel(float* __restrict__ out) {
    int i = blockIdx.x * 256 + threadIdx.x;  // 2,097,152 = 8192*256
    out[OFF_I + i] = (float)g_idx[i];
}

// ---------------- launch ----------------
extern "C" void kernel_launch(void* const* d_in, const int* in_sizes, int n_in,
                              void* d_out, int out_size) {
    const float* x  = (const float*)d_in[0];
    const float* w0 = (const float*)d_in[1];
    const float* b0 = (const float*)d_in[2];
    const float* w1 = (const float*)d_in[3];
    const float* b1 = (const float*)d_in[4];
    float* out = (float*)d_out;

    knn_kernel<<<dim3(4, TT, BB), 256>>>(x);
    wdiff_kernel<<<4, 128>>>(w0, w1);

    dim3 gg(8, 8, BB);
    dim3 gt(NN, BB);
    for (int t = 0; t < TT; ++t) {           // layer 0
        gemm_kernel<<<gg, 256>>>(0, t, x, w0, b0, w1, b1);  // U0
        gemm_kernel<<<gg, 256>>>(1, t, x, w0, b0, w1, b1);  // V0
        gate_kernel<<<gt, 128>>>(t, 0);
    }
    for (int t = 0; t < TT; ++t) {           // layer 1
        gemm_kernel<<<gg, 256>>>(2, t, x, w0, b0, w1, b1);  // U1
        gemm_kernel<<<gg, 256>>>(3, t, x, w0, b0, w1, b1);  // V1
        gate_kernel<<<gt, 128>>>(t, 1);
    }

    out1_pos_kernel<<<2048, 256>>>(x, out);
    out1_hs_kernel<<<dim3(32, 4, BB*TT), dim3(32, 32)>>>(out);
    hc_kernel<<<dim3(32, 4, BB), dim3(32, 32)>>>(out);
    idxf_kernel<<<8192, 256>>>(out);
}